// round 5
// baseline (speedup 1.0000x reference)
#include <cuda_runtime.h>
#include <cuda_bf16.h>
#include <math.h>

#define N_NODES 100000
#define E_EDGES 1600000
#define IN_F 20
#define H_F 64
#define NHEADS 4
#define HO_F 32
#define EPS_BN 1e-5f
#define SCAN_B 512
#define NB_SCAN ((N_NODES + SCAN_B - 1) / SCAN_B)   // 196
#define CAP 64                                      // smem exp-cache depth per node
#define PB_NODES 64                                 // nodes per block in gat_post

// ---------------- scratch (device globals; no allocation) ----------------
__device__ int    d_cnt[N_NODES];                   // self-resetting (zero after scan1)
__device__ int    d_rowptr[N_NODES + 1];
__device__ int    d_cursor[N_NODES];
__device__ int    d_bsum[NB_SCAN];
__device__ int    d_csr_src[E_EDGES];
__device__ float  d_aggrx[N_NODES * IN_F];
__device__ float  d_h1[N_NODES * H_F];
__device__ unsigned int d_h1bu[N_NODES * 32];       // h1 in bf16 (2 per uint), 12.8MB
__device__ float  d_u[512];                         // u_src[4][64], u_dst[4][64]
__device__ float4 d_asrc4[N_NODES];
__device__ float4 d_adst4[N_NODES];
__device__ unsigned int d_aggat_u[N_NODES * 128];   // alpha-agg h1 per head, bf16, 51.2MB
__device__ float  d_h2[N_NODES * H_F];
__device__ unsigned int d_h2bu[N_NODES * 32];       // h2 bf16
__device__ float  d_aggr2[N_NODES * H_F];

// ---------------- f32x2 helpers (sm_103 FFMA2) ----------------
__device__ __forceinline__ unsigned long long pk2(float a, float b) {
    unsigned long long r;
    asm("mov.b64 %0, {%1,%2};" : "=l"(r) : "f"(a), "f"(b));
    return r;
}
__device__ __forceinline__ unsigned long long fma2(unsigned long long a,
                                                   unsigned long long b,
                                                   unsigned long long c) {
    unsigned long long d;
    asm("fma.rn.f32x2 %0, %1, %2, %3;" : "=l"(d) : "l"(a), "l"(b), "l"(c));
    return d;
}
__device__ __forceinline__ float2 upk2(unsigned long long v) {
    float2 f;
    asm("mov.b64 {%0,%1}, %2;" : "=f"(f.x), "=f"(f.y) : "l"(v));
    return f;
}
__device__ __forceinline__ float2 bf2f(unsigned int u) {
    __nv_bfloat162 b = *reinterpret_cast<__nv_bfloat162*>(&u);
    return __bfloat1622float2(b);
}
__device__ __forceinline__ unsigned int f2bf(float a, float b) {
    __nv_bfloat162 p = __float22bfloat162_rn(make_float2(a, b));
    return *reinterpret_cast<unsigned int*>(&p);
}

// ---------------- CSR build ----------------
__global__ void k_count(const int* __restrict__ ei) {
    int e = blockIdx.x * blockDim.x + threadIdx.x;
    if (e >= E_EDGES) return;
    atomicAdd(&d_cnt[ei[E_EDGES + e]], 1);
}
__global__ void k_scan1() {
    __shared__ int sd[SCAN_B];
    int tid = threadIdx.x;
    int i = blockIdx.x * SCAN_B + tid;
    int v = (i < N_NODES) ? d_cnt[i] : 0;
    if (i < N_NODES) d_cnt[i] = 0;                   // self-reset for next replay
    sd[tid] = v;
    __syncthreads();
    for (int o = 1; o < SCAN_B; o <<= 1) {
        int t = (tid >= o) ? sd[tid - o] : 0;
        __syncthreads();
        sd[tid] += t;
        __syncthreads();
    }
    if (i < N_NODES) d_rowptr[i] = sd[tid] - v;
    if (tid == SCAN_B - 1) d_bsum[blockIdx.x] = sd[tid];
}
__global__ void k_scan23() {
    __shared__ int sd[256];
    int tid = threadIdx.x;
    int bv = (tid < NB_SCAN) ? d_bsum[tid] : 0;
    sd[tid] = bv;
    __syncthreads();
    for (int o = 1; o < 256; o <<= 1) {
        int t = (tid >= o) ? sd[tid - o] : 0;
        __syncthreads();
        sd[tid] += t;
        __syncthreads();
    }
    int off = (blockIdx.x == 0) ? 0 : sd[blockIdx.x - 1];
    for (int k = 0; k < SCAN_B; k += 256) {
        int i = blockIdx.x * SCAN_B + k + tid;
        if (i < N_NODES) {
            int r = d_rowptr[i] + off;
            d_rowptr[i] = r;
            d_cursor[i] = r;
        }
    }
    if (blockIdx.x == 0 && tid == 0) d_rowptr[N_NODES] = E_EDGES;
}
__global__ void k_scatter(const int* __restrict__ ei) {
    int e = blockIdx.x * blockDim.x + threadIdx.x;
    if (e >= E_EDGES) return;
    int s = ei[e], d = ei[E_EDGES + e];
    int pos = atomicAdd(&d_cursor[d], 1);
    d_csr_src[pos] = s;
}

// ---------------- precompute u_h = Wg_h @ att_h (folded attention vectors) -----
__global__ void k_prep(const float* __restrict__ Wg,
                       const float* __restrict__ att_src,
                       const float* __restrict__ att_dst) {
    int tid = blockIdx.x * blockDim.x + threadIdx.x;
    if (tid >= 512) return;
    int idx = tid & 255;
    int h = idx >> 6, k = idx & 63;
    const float* att = (tid < 256) ? att_src : att_dst;
    float acc = 0.0f;
#pragma unroll 8
    for (int d = 0; d < 64; d++)
        acc += Wg[k * 256 + h * 64 + d] * att[h * 64 + d];
    d_u[tid] = acc;
}

// ---------------- SAGE1 mean aggregation (CSR, warp per node, prefetched) ------
__global__ __launch_bounds__(256) void k_sage1_csr(const float* __restrict__ x) {
    int n = blockIdx.x * 8 + (threadIdx.x >> 5);
    int lane = threadIdx.x & 31;
    if (n >= N_NODES) return;
    int row = d_rowptr[n];
    int deg = d_rowptr[n + 1] - row;
    float acc = 0.0f;
    bool fl = lane < IN_F;
    for (int c = 0; c < deg; c += 32) {
        int idx = c + lane;
        int s_l = (idx < deg) ? __ldg(&d_csr_src[row + idx]) : 0;
        int kmax = min(32, deg - c);
        int s0 = __shfl_sync(0xffffffffu, s_l, 0);
        float v_cur = fl ? __ldg(&x[(size_t)s0 * IN_F + lane]) : 0.0f;
        for (int i = 0; i < kmax; i++) {
            float v_next = 0.0f;
            if (i + 1 < kmax) {
                int sn = __shfl_sync(0xffffffffu, s_l, i + 1);
                if (fl) v_next = __ldg(&x[(size_t)sn * IN_F + lane]);
            }
            acc += v_cur;
            v_cur = v_next;
        }
    }
    float inv = 1.0f / fmaxf((float)deg, 1.0f);
    if (fl) d_aggrx[(size_t)n * IN_F + lane] = acc * inv;
}

// ---------------- SAGE1 GEMM + BN + ReLU (+ bf16 copy of h1) ----------------
__global__ void k_sage1_gemm(const float* __restrict__ x,
                             const float* __restrict__ Wl, const float* __restrict__ Wr,
                             const float* __restrict__ b,
                             const float* __restrict__ g, const float* __restrict__ be,
                             const float* __restrict__ m, const float* __restrict__ v) {
    __shared__ float sWl[IN_F * H_F], sWr[IN_F * H_F];
    for (int i = threadIdx.x; i < IN_F * H_F; i += blockDim.x) { sWl[i] = Wl[i]; sWr[i] = Wr[i]; }
    __syncthreads();
    int t = blockIdx.x * blockDim.x + threadIdx.x;
    if (t >= N_NODES * H_F) return;
    int n = t >> 6, j = t & 63;
    const float* ax = d_aggrx + (size_t)n * IN_F;
    const float* xr = x + (size_t)n * IN_F;
    float acc = b[j];
#pragma unroll
    for (int k = 0; k < IN_F; k++) {
        acc = fmaf(ax[k], sWl[k * H_F + j], acc);
        acc = fmaf(xr[k], sWr[k * H_F + j], acc);
    }
    float sc = g[j] * rsqrtf(v[j] + EPS_BN);
    float y = fmaxf((acc - m[j]) * sc + be[j], 0.0f);
    d_h1[t] = y;
    // pack bf16 pairs (even lane stores {y_j, y_j+1})
    float ynext = __shfl_down_sync(0xffffffffu, y, 1);
    if ((j & 1) == 0) d_h1bu[t >> 1] = f2bf(y, ynext);
}

// ---------------- attention logits from folded u vectors (warp per node) -------
__global__ __launch_bounds__(256) void k_att() {
    int n = blockIdx.x * 8 + (threadIdx.x >> 5);
    int lane = threadIdx.x & 31;
    if (n >= N_NODES) return;
    float v0 = d_h1[(size_t)n * 64 + lane];
    float v1 = d_h1[(size_t)n * 64 + 32 + lane];
    float ps[4], pd[4];
#pragma unroll
    for (int h = 0; h < 4; h++) {
        ps[h] = v0 * __ldg(&d_u[h * 64 + lane]) + v1 * __ldg(&d_u[h * 64 + 32 + lane]);
        pd[h] = v0 * __ldg(&d_u[256 + h * 64 + lane]) + v1 * __ldg(&d_u[256 + h * 64 + 32 + lane]);
    }
#pragma unroll
    for (int o = 16; o; o >>= 1) {
#pragma unroll
        for (int h = 0; h < 4; h++) {
            ps[h] += __shfl_xor_sync(0xffffffffu, ps[h], o);
            pd[h] += __shfl_xor_sync(0xffffffffu, pd[h], o);
        }
    }
    if (lane == 0) {
        d_asrc4[n] = make_float4(ps[0], ps[1], ps[2], ps[3]);
        d_adst4[n] = make_float4(pd[0], pd[1], pd[2], pd[3]);
    }
}

// ---------------- GAT CSR: softmax + alpha-weighted h1 aggregation per head ----
__global__ __launch_bounds__(256) void k_gat_csr() {
    __shared__ float4 sExp[8][CAP];
    int w = threadIdx.x >> 5;
    int lane = threadIdx.x & 31;
    int n = blockIdx.x * 8 + w;
    if (n >= N_NODES) return;
    int row = d_rowptr[n];
    int deg = d_rowptr[n + 1] - row;
    float4 ad = d_adst4[n];

    // phase 1: denominators + exp cache
    float4 den = make_float4(0.f, 0.f, 0.f, 0.f);
    for (int c = 0; c < deg; c += 32) {
        int idx = c + lane;
        bool val = idx < deg;
        int s = val ? __ldg(&d_csr_src[row + idx]) : 0;
        float4 a = d_asrc4[s];
        float4 ex; float t;
        t = a.x + ad.x; t = t > 0.f ? t : 0.2f * t; ex.x = __expf(t);
        t = a.y + ad.y; t = t > 0.f ? t : 0.2f * t; ex.y = __expf(t);
        t = a.z + ad.z; t = t > 0.f ? t : 0.2f * t; ex.z = __expf(t);
        t = a.w + ad.w; t = t > 0.f ? t : 0.2f * t; ex.w = __expf(t);
        if (val) {
            den.x += ex.x; den.y += ex.y; den.z += ex.z; den.w += ex.w;
            if (idx < CAP) sExp[w][idx] = ex;
        }
    }
#pragma unroll
    for (int o = 16; o; o >>= 1) {
        den.x += __shfl_xor_sync(0xffffffffu, den.x, o);
        den.y += __shfl_xor_sync(0xffffffffu, den.y, o);
        den.z += __shfl_xor_sync(0xffffffffu, den.z, o);
        den.w += __shfl_xor_sync(0xffffffffu, den.w, o);
    }
    float4 invd = make_float4(1.0f / (den.x + 1e-16f), 1.0f / (den.y + 1e-16f),
                              1.0f / (den.z + 1e-16f), 1.0f / (den.w + 1e-16f));
    __syncwarp();

    // phase 2: gather bf16 h1 rows (lane holds dims 2l,2l+1), per-head fp32 acc
    float acc[8];
#pragma unroll
    for (int q = 0; q < 8; q++) acc[q] = 0.0f;
    for (int c = 0; c < deg; c += 32) {
        int idx = c + lane;
        int s_l = (idx < deg) ? __ldg(&d_csr_src[row + idx]) : 0;
        int kmax = min(32, deg - c);
        int s0 = __shfl_sync(0xffffffffu, s_l, 0);
        unsigned int v_cur = __ldg(&d_h1bu[(size_t)s0 * 32 + lane]);
        int s_cur = s0;
        for (int i = 0; i < kmax; i++) {
            unsigned int v_next = 0;
            int s_next = 0;
            if (i + 1 < kmax) {
                s_next = __shfl_sync(0xffffffffu, s_l, i + 1);
                v_next = __ldg(&d_h1bu[(size_t)s_next * 32 + lane]);
            }
            int eidx = c + i;
            float4 ex;
            if (eidx < CAP) {
                ex = sExp[w][eidx];
            } else {
                float4 a = d_asrc4[s_cur];
                float t;
                t = a.x + ad.x; t = t > 0.f ? t : 0.2f * t; ex.x = __expf(t);
                t = a.y + ad.y; t = t > 0.f ? t : 0.2f * t; ex.y = __expf(t);
                t = a.z + ad.z; t = t > 0.f ? t : 0.2f * t; ex.z = __expf(t);
                t = a.w + ad.w; t = t > 0.f ? t : 0.2f * t; ex.w = __expf(t);
            }
            float a0 = ex.x * invd.x, a1 = ex.y * invd.y;
            float a2 = ex.z * invd.z, a3 = ex.w * invd.w;
            float2 f = bf2f(v_cur);
            acc[0] = fmaf(a0, f.x, acc[0]); acc[1] = fmaf(a0, f.y, acc[1]);
            acc[2] = fmaf(a1, f.x, acc[2]); acc[3] = fmaf(a1, f.y, acc[3]);
            acc[4] = fmaf(a2, f.x, acc[4]); acc[5] = fmaf(a2, f.y, acc[5]);
            acc[6] = fmaf(a3, f.x, acc[6]); acc[7] = fmaf(a3, f.y, acc[7]);
            v_cur = v_next;
            s_cur = s_next;
        }
    }
#pragma unroll
    for (int h = 0; h < 4; h++)
        d_aggat_u[(size_t)n * 128 + h * 32 + lane] = f2bf(acc[h * 2], acc[h * 2 + 1]);
}

// ---------------- GAT post GEMM: out = mean_h(agg_h @ Wg_h), BN+ReLU -----------
// 64 nodes/block, 128 threads: j16 = tid&15 (4 output cols), g = tid>>4 (8 nodes)
__global__ __launch_bounds__(128) void k_gat_post(const float* __restrict__ Wg,
                                                  const float* __restrict__ bg,
                                                  const float* __restrict__ g2,
                                                  const float* __restrict__ be2,
                                                  const float* __restrict__ m2,
                                                  const float* __restrict__ v2) {
    __shared__ unsigned int sA[PB_NODES * 128];   // 32 KB: 64 nodes x 256 bf16
    int tid = threadIdx.x;
    int nbase = blockIdx.x * PB_NODES;
    {
        const uint4* src = (const uint4*)d_aggat_u;    // row = 32 uint4
        uint4* dst = (uint4*)sA;
#pragma unroll
        for (int r = 0; r < 16; r++) {
            int li = tid + r * 128;
            if (nbase + (li >> 5) < N_NODES) dst[li] = src[(size_t)nbase * 32 + li];
        }
    }
    __syncthreads();
    int j16 = tid & 15;
    int g = tid >> 4;
    const float4* Wg4 = (const float4*)Wg;
    unsigned long long accl[8], acch[8];
#pragma unroll
    for (int i = 0; i < 8; i++) { accl[i] = 0ull; acch[i] = 0ull; }
    const uint2* sA2 = (const uint2*)sA;               // per node: 64 uint2
#pragma unroll 4
    for (int kp = 0; kp < 64; kp++) {                  // kp -> bf16 idx 4kp..4kp+3
        int h = kp >> 4;
        int k = (kp & 15) * 4;
        const float4* wb = Wg4 + (size_t)k * 64 + h * 16 + j16;
        float4 w0 = __ldg(wb);
        float4 w1 = __ldg(wb + 64);
        float4 w2 = __ldg(wb + 128);
        float4 w3 = __ldg(wb + 192);
        unsigned long long w0l = pk2(w0.x, w0.y), w0h = pk2(w0.z, w0.w);
        unsigned long long w1l = pk2(w1.x, w1.y), w1h = pk2(w1.z, w1.w);
        unsigned long long w2l = pk2(w2.x, w2.y), w2h = pk2(w2.z, w2.w);
        unsigned long long w3l = pk2(w3.x, w3.y), w3h = pk2(w3.z, w3.w);
#pragma unroll
        for (int i = 0; i < 8; i++) {
            uint2 hv = sA2[(g * 8 + i) * 64 + kp];
            float2 f01 = bf2f(hv.x);
            float2 f23 = bf2f(hv.y);
            unsigned long long p;
            p = pk2(f01.x, f01.x); accl[i] = fma2(p, w0l, accl[i]); acch[i] = fma2(p, w0h, acch[i]);
            p = pk2(f01.y, f01.y); accl[i] = fma2(p, w1l, accl[i]); acch[i] = fma2(p, w1h, acch[i]);
            p = pk2(f23.x, f23.x); accl[i] = fma2(p, w2l, accl[i]); acch[i] = fma2(p, w2h, acch[i]);
            p = pk2(f23.y, f23.y); accl[i] = fma2(p, w3l, accl[i]); acch[i] = fma2(p, w3h, acch[i]);
        }
    }
    int jc = j16 * 4;
    float sc0 = __ldg(&g2[jc + 0]) * rsqrtf(__ldg(&v2[jc + 0]) + EPS_BN);
    float sc1 = __ldg(&g2[jc + 1]) * rsqrtf(__ldg(&v2[jc + 1]) + EPS_BN);
    float sc2 = __ldg(&g2[jc + 2]) * rsqrtf(__ldg(&v2[jc + 2]) + EPS_BN);
    float sc3 = __ldg(&g2[jc + 3]) * rsqrtf(__ldg(&v2[jc + 3]) + EPS_BN);
    float c0 = __ldg(&bg[jc + 0]) - __ldg(&m2[jc + 0]);
    float c1 = __ldg(&bg[jc + 1]) - __ldg(&m2[jc + 1]);
    float c2 = __ldg(&bg[jc + 2]) - __ldg(&m2[jc + 2]);
    float c3 = __ldg(&bg[jc + 3]) - __ldg(&m2[jc + 3]);
    float e0 = __ldg(&be2[jc + 0]), e1 = __ldg(&be2[jc + 1]);
    float e2 = __ldg(&be2[jc + 2]), e3 = __ldg(&be2[jc + 3]);
#pragma unroll
    for (int i = 0; i < 8; i++) {
        int n = nbase + g * 8 + i;
        if (n >= N_NODES) continue;
        float2 a01 = upk2(accl[i]);
        float2 a23 = upk2(acch[i]);
        float y0 = fmaxf((a01.x * 0.25f + c0) * sc0 + e0, 0.0f);
        float y1 = fmaxf((a01.y * 0.25f + c1) * sc1 + e1, 0.0f);
        float y2 = fmaxf((a23.x * 0.25f + c2) * sc2 + e2, 0.0f);
        float y3 = fmaxf((a23.y * 0.25f + c3) * sc3 + e3, 0.0f);
        *(float4*)&d_h2[(size_t)n * 64 + jc] = make_float4(y0, y1, y2, y3);
        uint2 ub;
        ub.x = f2bf(y0, y1);
        ub.y = f2bf(y2, y3);
        *(uint2*)&d_h2bu[(size_t)n * 32 + j16 * 2] = ub;
    }
}

// ---------------- SAGE3 mean aggregation (CSR, warp per node, bf16 gather) -----
__global__ __launch_bounds__(256) void k_sage3_csr() {
    int n = blockIdx.x * 8 + (threadIdx.x >> 5);
    int lane = threadIdx.x & 31;
    if (n >= N_NODES) return;
    int row = d_rowptr[n];
    int deg = d_rowptr[n + 1] - row;
    float ax = 0.0f, ay = 0.0f;
    for (int c = 0; c < deg; c += 32) {
        int idx = c + lane;
        int s_l = (idx < deg) ? __ldg(&d_csr_src[row + idx]) : 0;
        int kmax = min(32, deg - c);
        int s0 = __shfl_sync(0xffffffffu, s_l, 0);
        unsigned int v_cur = __ldg(&d_h2bu[(size_t)s0 * 32 + lane]);
        for (int i = 0; i < kmax; i++) {
            unsigned int v_next = 0;
            if (i + 1 < kmax) {
                int sn = __shfl_sync(0xffffffffu, s_l, i + 1);
                v_next = __ldg(&d_h2bu[(size_t)sn * 32 + lane]);
            }
            float2 f = bf2f(v_cur);
            ax += f.x; ay += f.y;
            v_cur = v_next;
        }
    }
    float inv = 1.0f / fmaxf((float)deg, 1.0f);
    *(float2*)&d_aggr2[(size_t)n * 64 + lane * 2] = make_float2(ax * inv, ay * inv);
}

// ---------------- SAGE3 GEMM + BN + ReLU + skip + classifier + log_softmax -----
__global__ __launch_bounds__(256) void k_sage3_cls(const float* __restrict__ x,
                             const float* __restrict__ Wl, const float* __restrict__ Wr,
                             const float* __restrict__ b,
                             const float* __restrict__ g, const float* __restrict__ be,
                             const float* __restrict__ m, const float* __restrict__ v,
                             const float* __restrict__ Wskip, const float* __restrict__ bskip,
                             const float* __restrict__ Wc1, const float* __restrict__ bc1,
                             const float* __restrict__ Wc2, const float* __restrict__ bc2,
                             float* __restrict__ out) {
    __shared__ float sWl[H_F * HO_F], sWr[H_F * HO_F], sWs[IN_F * HO_F];
    __shared__ float sW1[32 * 32], sb1[32], sW2[64];
    for (int i = threadIdx.x; i < H_F * HO_F; i += blockDim.x) { sWl[i] = Wl[i]; sWr[i] = Wr[i]; }
    for (int i = threadIdx.x; i < IN_F * HO_F; i += blockDim.x) sWs[i] = Wskip[i];
    for (int i = threadIdx.x; i < 32 * 32; i += blockDim.x) sW1[i] = Wc1[i];
    if (threadIdx.x < 32) sb1[threadIdx.x] = bc1[threadIdx.x];
    else if (threadIdx.x < 96) sW2[threadIdx.x - 32] = Wc2[threadIdx.x - 32];
    __syncthreads();
    int n = blockIdx.x * 8 + (threadIdx.x >> 5);
    int j = threadIdx.x & 31;
    if (n >= N_NODES) return;
    const float* ag = d_aggr2 + (size_t)n * H_F;
    const float* hr = d_h2 + (size_t)n * H_F;
    float acc = b[j];
#pragma unroll
    for (int k = 0; k < H_F; k++) {
        acc = fmaf(ag[k], sWl[k * HO_F + j], acc);
        acc = fmaf(hr[k], sWr[k * HO_F + j], acc);
    }
    float ident = bskip[j];
    const float* xr = x + (size_t)n * IN_F;
#pragma unroll
    for (int k = 0; k < IN_F; k++) ident = fmaf(xr[k], sWs[k * HO_F + j], ident);
    float sc = g[j] * rsqrtf(v[j] + EPS_BN);
    float y = (acc - m[j]) * sc + be[j];
    float hv = fmaxf(y, 0.0f) + ident;
    float s = sb1[j];
#pragma unroll
    for (int k = 0; k < 32; k++) {
        float bb = __shfl_sync(0xffffffffu, hv, k);
        s = fmaf(bb, sW1[k * 32 + j], s);
    }
    s = fmaxf(s, 0.0f);
    float p0 = s * sW2[j * 2];
    float p1 = s * sW2[j * 2 + 1];
#pragma unroll
    for (int o = 16; o; o >>= 1) {
        p0 += __shfl_down_sync(0xffffffffu, p0, o);
        p1 += __shfl_down_sync(0xffffffffu, p1, o);
    }
    if (j == 0) {
        float l0 = p0 + bc2[0], l1 = p1 + bc2[1];
        float mx = fmaxf(l0, l1);
        float lse = mx + logf(__expf(l0 - mx) + __expf(l1 - mx));
        out[(size_t)n * 2]     = l0 - lse;
        out[(size_t)n * 2 + 1] = l1 - lse;
    }
}

// ---------------- launch ----------------
extern "C" void kernel_launch(void* const* d_in, const int* in_sizes, int n_in,
                              void* d_out, int out_size) {
    const float* x       = (const float*)d_in[0];
    const int*   ei      = (const int*)d_in[1];
    const float* W1l     = (const float*)d_in[2];
    const float* W1r     = (const float*)d_in[3];
    const float* b1      = (const float*)d_in[4];
    const float* g1      = (const float*)d_in[5];
    const float* be1     = (const float*)d_in[6];
    const float* m1      = (const float*)d_in[7];
    const float* v1      = (const float*)d_in[8];
    const float* Wg      = (const float*)d_in[9];
    const float* att_src = (const float*)d_in[10];
    const float* att_dst = (const float*)d_in[11];
    const float* bg      = (const float*)d_in[12];
    const float* g2      = (const float*)d_in[13];
    const float* be2     = (const float*)d_in[14];
    const float* m2      = (const float*)d_in[15];
    const float* v2      = (const float*)d_in[16];
    const float* W3l     = (const float*)d_in[17];
    const float* W3r     = (const float*)d_in[18];
    const float* b3      = (const float*)d_in[19];
    const float* g3      = (const float*)d_in[20];
    const float* be3     = (const float*)d_in[21];
    const float* m3      = (const float*)d_in[22];
    const float* v3      = (const float*)d_in[23];
    const float* Wskip   = (const float*)d_in[24];
    const float* bskip   = (const float*)d_in[25];
    const float* Wc1     = (const float*)d_in[26];
    const float* bc1     = (const float*)d_in[27];
    const float* Wc2     = (const float*)d_in[28];
    const float* bc2     = (const float*)d_in[29];
    float* out = (float*)d_out;

    const int TPB = 256;
    k_count<<<(E_EDGES + TPB - 1) / TPB, TPB>>>(ei);
    k_scan1<<<NB_SCAN, SCAN_B>>>();
    k_scan23<<<NB_SCAN, 256>>>();
    k_scatter<<<(E_EDGES + TPB - 1) / TPB, TPB>>>(ei);
    k_prep<<<2, 256>>>(Wg, att_src, att_dst);
    k_sage1_csr<<<(N_NODES + 7) / 8, TPB>>>(x);
    k_sage1_gemm<<<(N_NODES * H_F + TPB - 1) / TPB, TPB>>>(x, W1l, W1r, b1, g1, be1, m1, v1);
    k_att<<<(N_NODES + 7) / 8, TPB>>>();
    k_gat_csr<<<(N_NODES + 7) / 8, TPB>>>();
    k_gat_post<<<(N_NODES + PB_NODES - 1) / PB_NODES, 128>>>(Wg, bg, g2, be2, m2, v2);
    k_sage3_csr<<<(N_NODES + 7) / 8, TPB>>>();
    k_sage3_cls<<<(N_NODES + 7) / 8, TPB>>>(x, W3l, W3r, b3, g3, be3, m3, v3, Wskip, bskip,
                                            Wc1, bc1, Wc2, bc2, out);
}

// round 7
// speedup vs baseline: 1.0837x; 1.0837x over previous
#include <cuda_runtime.h>
#include <cuda_bf16.h>
#include <math.h>
#include <stdint.h>

#define N_NODES 100000
#define E_EDGES 1600000
#define IN_F 20
#define H_F 64
#define NHEADS 4
#define HO_F 32
#define EPS_BN 1e-5f
#define SCAN_B 512
#define NB_SCAN ((N_NODES + SCAN_B - 1) / SCAN_B)   // 196
#define PB_NODES 64

// ---------------- scratch (device globals; no allocation) ----------------
__device__ int    d_cnt[N_NODES];                   // self-resetting (zero after scan1)
__device__ int    d_rowptr[N_NODES + 1];
__device__ int    d_cursor[N_NODES];
__device__ int    d_bsum[NB_SCAN];
__device__ int    d_csr_src[E_EDGES];
__device__ float  d_aggrx[N_NODES * IN_F];
__device__ float  d_h1[N_NODES * H_F];
__device__ unsigned int d_h1bu[N_NODES * 32];       // h1 bf16 pairs (12.8MB, L2-resident)
__device__ float  d_u[512];                         // folded att vectors
__device__ float4 d_asrc4[N_NODES];
__device__ float4 d_adst4[N_NODES];
__device__ unsigned int d_aggat_u[N_NODES * 128];   // [n][h][dims as bf16 pairs] (51.2MB)
__device__ float  d_h2[N_NODES * H_F];
__device__ unsigned int d_h2bu[N_NODES * 32];       // h2 bf16 pairs
__device__ float  d_aggr2[N_NODES * H_F];

// ---------------- helpers ----------------
__device__ __forceinline__ float2 bf2f(unsigned int u) {
    __nv_bfloat162 b = *reinterpret_cast<__nv_bfloat162*>(&u);
    return __bfloat1622float2(b);
}
__device__ __forceinline__ unsigned int f2bf(float a, float b) {
    __nv_bfloat162 p = __float22bfloat162_rn(make_float2(a, b));
    return *reinterpret_cast<unsigned int*>(&p);
}
__device__ __forceinline__ unsigned long long pk2(float a, float b) {
    unsigned long long r;
    asm("mov.b64 %0, {%1,%2};" : "=l"(r) : "f"(a), "f"(b));
    return r;
}
__device__ __forceinline__ unsigned long long fma2(unsigned long long a,
                                                   unsigned long long b,
                                                   unsigned long long c) {
    unsigned long long d;
    asm("fma.rn.f32x2 %0, %1, %2, %3;" : "=l"(d) : "l"(a), "l"(b), "l"(c));
    return d;
}
__device__ __forceinline__ float2 upk2(unsigned long long v) {
    float2 f;
    asm("mov.b64 {%0,%1}, %2;" : "=f"(f.x), "=f"(f.y) : "l"(v));
    return f;
}

// ---------------- CSR build ----------------
__global__ void k_count(const int* __restrict__ ei) {
    int e = blockIdx.x * blockDim.x + threadIdx.x;
    if (e >= E_EDGES) return;
    atomicAdd(&d_cnt[ei[E_EDGES + e]], 1);
}
__global__ void k_scan1() {
    __shared__ int sd[SCAN_B];
    int tid = threadIdx.x;
    int i = blockIdx.x * SCAN_B + tid;
    int v = (i < N_NODES) ? d_cnt[i] : 0;
    if (i < N_NODES) d_cnt[i] = 0;
    sd[tid] = v;
    __syncthreads();
    for (int o = 1; o < SCAN_B; o <<= 1) {
        int t = (tid >= o) ? sd[tid - o] : 0;
        __syncthreads();
        sd[tid] += t;
        __syncthreads();
    }
    if (i < N_NODES) d_rowptr[i] = sd[tid] - v;
    if (tid == SCAN_B - 1) d_bsum[blockIdx.x] = sd[tid];
}
__global__ void k_scan23() {
    __shared__ int sd[256];
    int tid = threadIdx.x;
    int bv = (tid < NB_SCAN) ? d_bsum[tid] : 0;
    sd[tid] = bv;
    __syncthreads();
    for (int o = 1; o < 256; o <<= 1) {
        int t = (tid >= o) ? sd[tid - o] : 0;
        __syncthreads();
        sd[tid] += t;
        __syncthreads();
    }
    int off = (blockIdx.x == 0) ? 0 : sd[blockIdx.x - 1];
    for (int k = 0; k < SCAN_B; k += 256) {
        int i = blockIdx.x * SCAN_B + k + tid;
        if (i < N_NODES) {
            int r = d_rowptr[i] + off;
            d_rowptr[i] = r;
            d_cursor[i] = r;
        }
    }
    if (blockIdx.x == 0 && tid == 0) d_rowptr[N_NODES] = E_EDGES;
}
__global__ void k_scatter(const int* __restrict__ ei) {
    int e = blockIdx.x * blockDim.x + threadIdx.x;
    if (e >= E_EDGES) return;
    int s = ei[e], d = ei[E_EDGES + e];
    int pos = atomicAdd(&d_cursor[d], 1);
    d_csr_src[pos] = s;
}

// ---------------- prep: folded attention vectors u_h = Wg_h @ att_h ------------
__global__ void k_prep(const float* __restrict__ Wg,
                       const float* __restrict__ att_src,
                       const float* __restrict__ att_dst) {
    int tid = blockIdx.x * blockDim.x + threadIdx.x;
    if (tid >= 512) return;
    int idx = tid & 255;
    int h = idx >> 6, k = idx & 63;
    const float* att = (tid < 256) ? att_src : att_dst;
    float acc = 0.0f;
#pragma unroll 8
    for (int d = 0; d < 64; d++)
        acc += Wg[k * 256 + h * 64 + d] * att[h * 64 + d];
    d_u[tid] = acc;
}

// ---------------- SAGE1 mean aggregation (CSR, warp/node, 2 edges/iter) --------
__global__ __launch_bounds__(256) void k_sage1_csr(const float* __restrict__ x) {
    int n = blockIdx.x * 8 + (threadIdx.x >> 5);
    int lane = threadIdx.x & 31;
    if (n >= N_NODES) return;
    int row = d_rowptr[n];
    int deg = d_rowptr[n + 1] - row;
    int p = lane >> 4, f = lane & 15;
    const float2* x2 = (const float2*)x;   // row = 10 float2
    float2 acc = make_float2(0.f, 0.f);
    for (int c = 0; c < deg; c += 32) {
        int idx = c + lane;
        bool val = idx < deg;
        int s_l = val ? __ldg(&d_csr_src[row + idx]) : 0;
        float onev = val ? 1.0f : 0.0f;
        int kmax = min(32, deg - c);
        for (int i = 0; i < kmax; i += 2) {
            int e = i + p;
            int s = __shfl_sync(0xffffffffu, s_l, e);
            float g = __shfl_sync(0xffffffffu, onev, e);
            if (f < 10) {
                float2 vv = __ldg(&x2[(size_t)s * 10 + f]);
                acc.x = fmaf(g, vv.x, acc.x);
                acc.y = fmaf(g, vv.y, acc.y);
            }
        }
    }
    acc.x += __shfl_xor_sync(0xffffffffu, acc.x, 16);
    acc.y += __shfl_xor_sync(0xffffffffu, acc.y, 16);
    if (p == 0 && f < 10) {
        float inv = 1.0f / fmaxf((float)deg, 1.0f);
        ((float2*)d_aggrx)[(size_t)n * 10 + f] = make_float2(acc.x * inv, acc.y * inv);
    }
}

// ---------------- SAGE1 GEMM + BN + ReLU + bf16 pack ----------------
__global__ void k_sage1_gemm(const float* __restrict__ x,
                             const float* __restrict__ Wl, const float* __restrict__ Wr,
                             const float* __restrict__ b,
                             const float* __restrict__ g, const float* __restrict__ be,
                             const float* __restrict__ m, const float* __restrict__ v) {
    __shared__ float sWl[IN_F * H_F], sWr[IN_F * H_F];
    for (int i = threadIdx.x; i < IN_F * H_F; i += blockDim.x) { sWl[i] = Wl[i]; sWr[i] = Wr[i]; }
    __syncthreads();
    int t = blockIdx.x * blockDim.x + threadIdx.x;
    if (t >= N_NODES * H_F) return;
    int n = t >> 6, j = t & 63;
    const float* ax = d_aggrx + (size_t)n * IN_F;
    const float* xr = x + (size_t)n * IN_F;
    float acc = b[j];
#pragma unroll
    for (int k = 0; k < IN_F; k++) {
        acc = fmaf(ax[k], sWl[k * H_F + j], acc);
        acc = fmaf(xr[k], sWr[k * H_F + j], acc);
    }
    float sc = g[j] * rsqrtf(v[j] + EPS_BN);
    float y = fmaxf((acc - m[j]) * sc + be[j], 0.0f);
    d_h1[t] = y;
    float ynext = __shfl_down_sync(0xffffffffu, y, 1);
    if ((j & 1) == 0) d_h1bu[t >> 1] = f2bf(y, ynext);
}

// ---------------- attention logits from folded u vectors (warp per node) -------
__global__ __launch_bounds__(256) void k_att() {
    int n = blockIdx.x * 8 + (threadIdx.x >> 5);
    int lane = threadIdx.x & 31;
    if (n >= N_NODES) return;
    float v0 = d_h1[(size_t)n * 64 + lane];
    float v1 = d_h1[(size_t)n * 64 + 32 + lane];
    float ps[4], pd[4];
#pragma unroll
    for (int h = 0; h < 4; h++) {
        ps[h] = v0 * __ldg(&d_u[h * 64 + lane]) + v1 * __ldg(&d_u[h * 64 + 32 + lane]);
        pd[h] = v0 * __ldg(&d_u[256 + h * 64 + lane]) + v1 * __ldg(&d_u[256 + h * 64 + 32 + lane]);
    }
#pragma unroll
    for (int o = 16; o; o >>= 1) {
#pragma unroll
        for (int h = 0; h < 4; h++) {
            ps[h] += __shfl_xor_sync(0xffffffffu, ps[h], o);
            pd[h] += __shfl_xor_sync(0xffffffffu, pd[h], o);
        }
    }
    if (lane == 0) {
        d_asrc4[n] = make_float4(ps[0], ps[1], ps[2], ps[3]);
        d_adst4[n] = make_float4(pd[0], pd[1], pd[2], pd[3]);
    }
}

// ---------------- GAT fused single-pass: unnormalized agg + denom --------------
// warp per node; 2 edges per iteration (half-warp each, 16 lanes x uint2 = 128B row)
__global__ __launch_bounds__(256) void k_gat_csr() {
    int w = threadIdx.x >> 5, lane = threadIdx.x & 31;
    int n = blockIdx.x * 8 + w;
    if (n >= N_NODES) return;
    int row = d_rowptr[n];
    int deg = d_rowptr[n + 1] - row;
    float4 ad = d_adst4[n];
    int p = lane >> 4, f = lane & 15;
    const uint2* h1b2 = (const uint2*)d_h1bu;   // row = 16 uint2
    float acc[16];
#pragma unroll
    for (int q = 0; q < 16; q++) acc[q] = 0.0f;
    float4 den = make_float4(0.f, 0.f, 0.f, 0.f);
    for (int c = 0; c < deg; c += 32) {
        int idx = c + lane;
        bool val = idx < deg;
        int s_l = val ? __ldg(&d_csr_src[row + idx]) : 0;
        // lane-parallel exp for all 32 edges of this chunk (MLP=32)
        float4 a = d_asrc4[s_l];
        float t; float4 ex;
        t = a.x + ad.x; t = t > 0.f ? t : 0.2f * t; ex.x = __expf(t);
        t = a.y + ad.y; t = t > 0.f ? t : 0.2f * t; ex.y = __expf(t);
        t = a.z + ad.z; t = t > 0.f ? t : 0.2f * t; ex.z = __expf(t);
        t = a.w + ad.w; t = t > 0.f ? t : 0.2f * t; ex.w = __expf(t);
        if (!val) { ex.x = 0.f; ex.y = 0.f; ex.z = 0.f; ex.w = 0.f; }
        den.x += ex.x; den.y += ex.y; den.z += ex.z; den.w += ex.w;
        int kmax = min(32, deg - c);
        for (int i = 0; i < kmax; i += 2) {
            int e = i + p;      // <= 31 always
            int s = __shfl_sync(0xffffffffu, s_l, e);
            float e0 = __shfl_sync(0xffffffffu, ex.x, e);
            float e1 = __shfl_sync(0xffffffffu, ex.y, e);
            float e2 = __shfl_sync(0xffffffffu, ex.z, e);
            float e3 = __shfl_sync(0xffffffffu, ex.w, e);
            uint2 hv = __ldg(&h1b2[(size_t)s * 16 + f]);
            float2 f01 = bf2f(hv.x), f23 = bf2f(hv.y);
            acc[0]  = fmaf(e0, f01.x, acc[0]);  acc[1]  = fmaf(e0, f01.y, acc[1]);
            acc[2]  = fmaf(e0, f23.x, acc[2]);  acc[3]  = fmaf(e0, f23.y, acc[3]);
            acc[4]  = fmaf(e1, f01.x, acc[4]);  acc[5]  = fmaf(e1, f01.y, acc[5]);
            acc[6]  = fmaf(e1, f23.x, acc[6]);  acc[7]  = fmaf(e1, f23.y, acc[7]);
            acc[8]  = fmaf(e2, f01.x, acc[8]);  acc[9]  = fmaf(e2, f01.y, acc[9]);
            acc[10] = fmaf(e2, f23.x, acc[10]); acc[11] = fmaf(e2, f23.y, acc[11]);
            acc[12] = fmaf(e3, f01.x, acc[12]); acc[13] = fmaf(e3, f01.y, acc[13]);
            acc[14] = fmaf(e3, f23.x, acc[14]); acc[15] = fmaf(e3, f23.y, acc[15]);
        }
    }
#pragma unroll
    for (int o = 16; o; o >>= 1) {
        den.x += __shfl_xor_sync(0xffffffffu, den.x, o);
        den.y += __shfl_xor_sync(0xffffffffu, den.y, o);
        den.z += __shfl_xor_sync(0xffffffffu, den.z, o);
        den.w += __shfl_xor_sync(0xffffffffu, den.w, o);
    }
#pragma unroll
    for (int q = 0; q < 16; q++) acc[q] += __shfl_xor_sync(0xffffffffu, acc[q], 16);
    if (p == 0) {
        float id0 = 1.0f / (den.x + 1e-16f);
        float id1 = 1.0f / (den.y + 1e-16f);
        float id2 = 1.0f / (den.z + 1e-16f);
        float id3 = 1.0f / (den.w + 1e-16f);
        uint2* ag2 = (uint2*)d_aggat_u;     // row = 64 uint2 ([h][16 uint2])
        ag2[(size_t)n * 64 + 0 * 16 + f] = make_uint2(f2bf(acc[0] * id0, acc[1] * id0),
                                                      f2bf(acc[2] * id0, acc[3] * id0));
        ag2[(size_t)n * 64 + 1 * 16 + f] = make_uint2(f2bf(acc[4] * id1, acc[5] * id1),
                                                      f2bf(acc[6] * id1, acc[7] * id1));
        ag2[(size_t)n * 64 + 2 * 16 + f] = make_uint2(f2bf(acc[8] * id2, acc[9] * id2),
                                                      f2bf(acc[10] * id2, acc[11] * id2));
        ag2[(size_t)n * 64 + 3 * 16 + f] = make_uint2(f2bf(acc[12] * id3, acc[13] * id3),
                                                      f2bf(acc[14] * id3, acc[15] * id3));
    }
}

// ---------------- GAT post GEMM: out = mean_h(agg_h @ Wg_h), BN+ReLU -----------
// 64 nodes/block, 128 threads: j16 = tid&15 (4 output cols), g = tid>>4 (8 nodes)
__global__ __launch_bounds__(128) void k_gat_post(const float* __restrict__ Wg,
                                                  const float* __restrict__ bg,
                                                  const float* __restrict__ g2,
                                                  const float* __restrict__ be2,
                                                  const float* __restrict__ m2,
                                                  const float* __restrict__ v2) {
    __shared__ unsigned int sA[PB_NODES * 128];   // 32 KB: 64 nodes x 256 bf16
    int tid = threadIdx.x;
    int nbase = blockIdx.x * PB_NODES;
    {
        const uint4* src = (const uint4*)d_aggat_u;    // row = 32 uint4
        uint4* dst = (uint4*)sA;
#pragma unroll
        for (int r = 0; r < 16; r++) {
            int li = tid + r * 128;
            if (nbase + (li >> 5) < N_NODES) dst[li] = src[(size_t)nbase * 32 + li];
        }
    }
    __syncthreads();
    int j16 = tid & 15;
    int g = tid >> 4;
    const float4* Wg4 = (const float4*)Wg;
    unsigned long long accl[8], acch[8];
#pragma unroll
    for (int i = 0; i < 8; i++) { accl[i] = 0ull; acch[i] = 0ull; }
    const uint2* sA2 = (const uint2*)sA;               // per node: 64 uint2
#pragma unroll 4
    for (int kp = 0; kp < 64; kp++) {                  // kp -> bf16 idx 4kp..4kp+3
        int h = kp >> 4;
        int k = (kp & 15) * 4;
        const float4* wb = Wg4 + (size_t)k * 64 + h * 16 + j16;
        float4 w0 = __ldg(wb);
        float4 w1 = __ldg(wb + 64);
        float4 w2 = __ldg(wb + 128);
        float4 w3 = __ldg(wb + 192);
        unsigned long long w0l = pk2(w0.x, w0.y), w0h = pk2(w0.z, w0.w);
        unsigned long long w1l = pk2(w1.x, w1.y), w1h = pk2(w1.z, w1.w);
        unsigned long long w2l = pk2(w2.x, w2.y), w2h = pk2(w2.z, w2.w);
        unsigned long long w3l = pk2(w3.x, w3.y), w3h = pk2(w3.z, w3.w);
#pragma unroll
        for (int i = 0; i < 8; i++) {
            uint2 hv = sA2[(g * 8 + i) * 64 + kp];
            float2 f01 = bf2f(hv.x);
            float2 f23 = bf2f(hv.y);
            unsigned long long p;
            p = pk2(f01.x, f01.x); accl[i] = fma2(p, w0l, accl[i]); acch[i] = fma2(p, w0h, acch[i]);
            p = pk2(f01.y, f01.y); accl[i] = fma2(p, w1l, accl[i]); acch[i] = fma2(p, w1h, acch[i]);
            p = pk2(f23.x, f23.x); accl[i] = fma2(p, w2l, accl[i]); acch[i] = fma2(p, w2h, acch[i]);
            p = pk2(f23.y, f23.y); accl[i] = fma2(p, w3l, accl[i]); acch[i] = fma2(p, w3h, acch[i]);
        }
    }
    int jc = j16 * 4;
    float sc0 = __ldg(&g2[jc + 0]) * rsqrtf(__ldg(&v2[jc + 0]) + EPS_BN);
    float sc1 = __ldg(&g2[jc + 1]) * rsqrtf(__ldg(&v2[jc + 1]) + EPS_BN);
    float sc2 = __ldg(&g2[jc + 2]) * rsqrtf(__ldg(&v2[jc + 2]) + EPS_BN);
    float sc3 = __ldg(&g2[jc + 3]) * rsqrtf(__ldg(&v2[jc + 3]) + EPS_BN);
    float c0 = __ldg(&bg[jc + 0]) - __ldg(&m2[jc + 0]);
    float c1 = __ldg(&bg[jc + 1]) - __ldg(&m2[jc + 1]);
    float c2 = __ldg(&bg[jc + 2]) - __ldg(&m2[jc + 2]);
    float c3 = __ldg(&bg[jc + 3]) - __ldg(&m2[jc + 3]);
    float e0 = __ldg(&be2[jc + 0]), e1 = __ldg(&be2[jc + 1]);
    float e2 = __ldg(&be2[jc + 2]), e3 = __ldg(&be2[jc + 3]);
#pragma unroll
    for (int i = 0; i < 8; i++) {
        int n = nbase + g * 8 + i;
        if (n >= N_NODES) continue;
        float2 a01 = upk2(accl[i]);
        float2 a23 = upk2(acch[i]);
        float y0 = fmaxf((a01.x * 0.25f + c0) * sc0 + e0, 0.0f);
        float y1 = fmaxf((a01.y * 0.25f + c1) * sc1 + e1, 0.0f);
        float y2 = fmaxf((a23.x * 0.25f + c2) * sc2 + e2, 0.0f);
        float y3 = fmaxf((a23.y * 0.25f + c3) * sc3 + e3, 0.0f);
        *(float4*)&d_h2[(size_t)n * 64 + jc] = make_float4(y0, y1, y2, y3);
        uint2 ub;
        ub.x = f2bf(y0, y1);
        ub.y = f2bf(y2, y3);
        *(uint2*)&d_h2bu[(size_t)n * 32 + j16 * 2] = ub;
    }
}

// ---------------- SAGE3 mean aggregation (CSR, warp/node, 2 edges/iter) --------
__global__ __launch_bounds__(256) void k_sage3_csr() {
    int n = blockIdx.x * 8 + (threadIdx.x >> 5);
    int lane = threadIdx.x & 31;
    if (n >= N_NODES) return;
    int row = d_rowptr[n];
    int deg = d_rowptr[n + 1] - row;
    int p = lane >> 4, f = lane & 15;
    const uint2* h2b2 = (const uint2*)d_h2bu;   // row = 16 uint2
    float4 acc = make_float4(0.f, 0.f, 0.f, 0.f);
    for (int c = 0; c < deg; c += 32) {
        int idx = c + lane;
        bool val = idx < deg;
        int s_l = val ? __ldg(&d_csr_src[row + idx]) : 0;
        float onev = val ? 1.0f : 0.0f;
        int kmax = min(32, deg - c);
        for (int i = 0; i < kmax; i += 2) {
            int e = i + p;
            int s = __shfl_sync(0xffffffffu, s_l, e);
            float g = __shfl_sync(0xffffffffu, onev, e);
            uint2 hv = __ldg(&h2b2[(size_t)s * 16 + f]);
            float2 f01 = bf2f(hv.x), f23 = bf2f(hv.y);
            acc.x = fmaf(g, f01.x, acc.x);
            acc.y = fmaf(g, f01.y, acc.y);
            acc.z = fmaf(g, f23.x, acc.z);
            acc.w = fmaf(g, f23.y, acc.w);
        }
    }
    acc.x += __shfl_xor_sync(0xffffffffu, acc.x, 16);
    acc.y += __shfl_xor_sync(0xffffffffu, acc.y, 16);
    acc.z += __shfl_xor_sync(0xffffffffu, acc.z, 16);
    acc.w += __shfl_xor_sync(0xffffffffu, acc.w, 16);
    if (p == 0) {
        float inv = 1.0f / fmaxf((float)deg, 1.0f);
        ((float4*)d_aggr2)[(size_t)n * 16 + f] =
            make_float4(acc.x * inv, acc.y * inv, acc.z * inv, acc.w * inv);
    }
}

// ---------------- SAGE3 GEMM + BN + ReLU + skip + classifier + log_softmax -----
__global__ __launch_bounds__(256) void k_sage3_cls(const float* __restrict__ x,
                             const float* __restrict__ Wl, const float* __restrict__ Wr,
                             const float* __restrict__ b,
                             const float* __restrict__ g, const float* __restrict__ be,
                             const float* __restrict__ m, const float* __restrict__ v,
                             const float* __restrict__ Wskip, const float* __restrict__ bskip,
                             const float* __restrict__ Wc1, const float* __restrict__ bc1,
                             const float* __restrict__ Wc2, const float* __restrict__ bc2,
                             float* __restrict__ out) {
    __shared__ float sWl[H_F * HO_F], sWr[H_F * HO_F], sWs[IN_F * HO_F];
    __shared__ float sW1[32 * 32], sb1[32], sW2[64];
    for (int i = threadIdx.x; i < H_F * HO_F; i += blockDim.x) { sWl[i] = Wl[i]; sWr[i] = Wr[i]; }
    for (int i = threadIdx.x; i < IN_F * HO_F; i += blockDim.x) sWs[i] = Wskip[i];
    for (int i = threadIdx.x; i < 32 * 32; i += blockDim.x) sW1[i] = Wc1[i];
    if (threadIdx.x < 32) sb1[threadIdx.x] = bc1[threadIdx.x];
    else if (threadIdx.x < 96) sW2[threadIdx.x - 32] = Wc2[threadIdx.x - 32];
    __syncthreads();
    int n = blockIdx.x * 8 + (threadIdx.x >> 5);
    int j = threadIdx.x & 31;
    if (n >= N_NODES) return;
    const float* ag = d_aggr2 + (size_t)n * H_F;
    const float* hr = d_h2 + (size_t)n * H_F;
    float acc = b[j];
#pragma unroll
    for (int k = 0; k < H_F; k++) {
        acc = fmaf(ag[k], sWl[k * HO_F + j], acc);
        acc = fmaf(hr[k], sWr[k * HO_F + j], acc);
    }
    float ident = bskip[j];
    const float* xr = x + (size_t)n * IN_F;
#pragma unroll
    for (int k = 0; k < IN_F; k++) ident = fmaf(xr[k], sWs[k * HO_F + j], ident);
    float sc = g[j] * rsqrtf(v[j] + EPS_BN);
    float y = (acc - m[j]) * sc + be[j];
    float hv = fmaxf(y, 0.0f) + ident;
    float s = sb1[j];
#pragma unroll
    for (int k = 0; k < 32; k++) {
        float bb = __shfl_sync(0xffffffffu, hv, k);
        s = fmaf(bb, sW1[k * 32 + j], s);
    }
    s = fmaxf(s, 0.0f);
    float p0 = s * sW2[j * 2];
    float p1 = s * sW2[j * 2 + 1];
#pragma unroll
    for (int o = 16; o; o >>= 1) {
        p0 += __shfl_down_sync(0xffffffffu, p0, o);
        p1 += __shfl_down_sync(0xffffffffu, p1, o);
    }
    if (j == 0) {
        float l0 = p0 + bc2[0], l1 = p1 + bc2[1];
        float mx = fmaxf(l0, l1);
        float lse = mx + logf(__expf(l0 - mx) + __expf(l1 - mx));
        out[(size_t)n * 2]     = l0 - lse;
        out[(size_t)n * 2 + 1] = l1 - lse;
    }
}

// ---------------- launch ----------------
extern "C" void kernel_launch(void* const* d_in, const int* in_sizes, int n_in,
                              void* d_out, int out_size) {
    const float* x       = (const float*)d_in[0];
    const int*   ei      = (const int*)d_in[1];
    const float* W1l     = (const float*)d_in[2];
    const float* W1r     = (const float*)d_in[3];
    const float* b1      = (const float*)d_in[4];
    const float* g1      = (const float*)d_in[5];
    const float* be1     = (const float*)d_in[6];
    const float* m1      = (const float*)d_in[7];
    const float* v1      = (const float*)d_in[8];
    const float* Wg      = (const float*)d_in[9];
    const float* att_src = (const float*)d_in[10];
    const float* att_dst = (const float*)d_in[11];
    const float* bg      = (const float*)d_in[12];
    const float* g2      = (const float*)d_in[13];
    const float* be2     = (const float*)d_in[14];
    const float* m2      = (const float*)d_in[15];
    const float* v2      = (const float*)d_in[16];
    const float* W3l     = (const float*)d_in[17];
    const float* W3r     = (const float*)d_in[18];
    const float* b3      = (const float*)d_in[19];
    const float* g3      = (const float*)d_in[20];
    const float* be3     = (const float*)d_in[21];
    const float* m3      = (const float*)d_in[22];
    const float* v3      = (const float*)d_in[23];
    const float* Wskip   = (const float*)d_in[24];
    const float* bskip   = (const float*)d_in[25];
    const float* Wc1     = (const float*)d_in[26];
    const float* bc1     = (const float*)d_in[27];
    const float* Wc2     = (const float*)d_in[28];
    const float* bc2     = (const float*)d_in[29];
    float* out = (float*)d_out;

    const int TPB = 256;
    k_count<<<(E_EDGES + TPB - 1) / TPB, TPB>>>(ei);
    k_scan1<<<NB_SCAN, SCAN_B>>>();
    k_scan23<<<NB_SCAN, 256>>>();
    k_scatter<<<(E_EDGES + TPB - 1) / TPB, TPB>>>(ei);
    k_prep<<<2, 256>>>(Wg, att_src, att_dst);
    k_sage1_csr<<<(N_NODES + 7) / 8, TPB>>>(x);
    k_sage1_gemm<<<(N_NODES * H_F + TPB - 1) / TPB, TPB>>>(x, W1l, W1r, b1, g1, be1, m1, v1);
    k_att<<<(N_NODES + 7) / 8, TPB>>>();
    k_gat_csr<<<(N_NODES + 7) / 8, TPB>>>();
    k_gat_post<<<(N_NODES + PB_NODES - 1) / PB_NODES, 128>>>(Wg, bg, g2, be2, m2, v2);
    k_sage3_csr<<<(N_NODES + 7) / 8, TPB>>>();
    k_sage3_cls<<<(N_NODES + 7) / 8, TPB>>>(x, W3l, W3r, b3, g3, be3, m3, v3, Wskip, bskip,
                                            Wc1, bc1, Wc2, bc2, out);
}